// round 14
// baseline (speedup 1.0000x reference)
#include <cuda_runtime.h>
#include <stdint.h>

// Problem shape (static)
#define B 32
#define L 4
#define S 512
#define D 768
#define G 24        // NUM_SEGMENTS
#define NCHUNK 18   // 18 * 32 = 576 CTAs ~= one wave at occ 4 (256 thr)

// Output layout (float32, tuple-order concat):
//   word [B,S,D] | sent [B,D] | seg [B,G,D] | mask [B,G]
#define OFF_SENT ((size_t)B * S * D)
#define OFF_SEG  (OFF_SENT + (size_t)B * D)
#define OFF_MASK (OFF_SEG + (size_t)B * G * D)
// region accumulated with atomics -> must start at zero: sent + seg (contiguous)
#define ZERO_N   ((size_t)B * D + (size_t)B * G * D)

#define LS (S * D)   // layer stride in floats (393216)

// load one token's 4 layers x 3 columns into buf[12]
#define LOAD_TOK(buf, t) do {                                  \
    const float* _p = ep + (t) * D;                            \
    buf[0]  = _p[0];           buf[1]  = _p[256];           buf[2]  = _p[512];           \
    buf[3]  = _p[LS];          buf[4]  = _p[LS + 256];      buf[5]  = _p[LS + 512];      \
    buf[6]  = _p[2 * LS];      buf[7]  = _p[2 * LS + 256];  buf[8]  = _p[2 * LS + 512];  \
    buf[9]  = _p[3 * LS];      buf[10] = _p[3 * LS + 256];  buf[11] = _p[3 * LS + 512];  \
} while (0)

// layer-sum of buf into e0/e1/e2 (3 columns)
#define ESUM(buf, e0, e1, e2) do {                             \
    e0 = (buf[0] + buf[3]) + (buf[6] + buf[9]);                \
    e1 = (buf[1] + buf[4]) + (buf[7] + buf[10]);               \
    e2 = (buf[2] + buf[5]) + (buf[8] + buf[11]);               \
} while (0)

// run-length flush for one token (block-uniform control flow)
#define FLUSH(tok, e0, e1, e2) do {                            \
    const int _g = s_tg[tok];                                  \
    if (_g != cur_g) {                                         \
        const int _wo = cur_g * D;                             \
        wout[_wo] = wacc0; wout[_wo + 256] = wacc1; wout[_wo + 512] = wacc2; \
        const int _mysg = s_sg[cur_g];                         \
        if (_mysg != cur_sg) {                                 \
            const int _go = cur_sg * D;                        \
            atomicAdd(&gout[_go], gacc0);                      \
            atomicAdd(&gout[_go + 256], gacc1);                \
            atomicAdd(&gout[_go + 512], gacc2);                \
            gacc0 = gacc1 = gacc2 = 0.f;                       \
            cur_sg = _mysg;                                    \
        }                                                      \
        gacc0 += wacc0; gacc1 += wacc1; gacc2 += wacc2;        \
        for (int _z = cur_g + 1; _z < _g; ++_z) {              \
            const int _zo = _z * D;                            \
            wout[_zo] = 0.f; wout[_zo + 256] = 0.f; wout[_zo + 512] = 0.f; \
        }                                                      \
        wacc0 = wacc1 = wacc2 = 0.f;                           \
        cur_g = _g;                                            \
    }                                                          \
    wacc0 += e0; wacc1 += e1; wacc2 += e2;                     \
    sent0 += e0; sent1 += e1; sent2 += e2;                     \
} while (0)

// grid: (NCHUNK, B), block: 256 threads (each owns 3 d columns: tid, tid+256, tid+512)
__global__ void __launch_bounds__(256, 4)
bert_agg_kernel(const float* __restrict__ emb,
                const int*   __restrict__ tg,
                const int*   __restrict__ sg,
                float*       __restrict__ out)
{
    const int b     = blockIdx.y;
    const int chunk = blockIdx.x;
    const int tid   = threadIdx.x;

    __shared__ int s_tg[S];
    __shared__ int s_sg[S];
    for (int i = tid; i < S; i += 256) {
        s_tg[i] = tg[b * S + i];
        s_sg[i] = sg[b * S + i];
    }
    __syncthreads();

    // ---- chunk bounds, snapped to word-run boundaries (block-uniform) ----
    int ts = (chunk * S) / NCHUNK;
    while (ts > 0 && ts < S && s_tg[ts] == s_tg[ts - 1]) ++ts;
    int te;
    if (chunk == NCHUNK - 1) {
        te = S;
    } else {
        te = ((chunk + 1) * S) / NCHUNK;
        while (te < S && s_tg[te] == s_tg[te - 1]) ++te;
    }

    // 32-bit offsets (max index < 2^26)
    const float* ep  = emb + (b * L * S * D) + tid;
    float*      wout = out + (b * S * D) + tid;
    float*      gout = out + OFF_SEG + (b * G * D) + tid;

    if (ts < te) {
        // leading word gap (only the chunk starting at token 0)
        if (ts == 0) {
            const int firstw = s_tg[0];
            for (int z = 0; z < firstw; ++z) {
                const int zo = z * D;
                wout[zo] = 0.f; wout[zo + 256] = 0.f; wout[zo + 512] = 0.f;
            }
        }

        float sent0 = 0.f, sent1 = 0.f, sent2 = 0.f;
        int   cur_g  = s_tg[ts];
        float wacc0 = 0.f, wacc1 = 0.f, wacc2 = 0.f;
        int   cur_sg = s_sg[cur_g];
        float gacc0 = 0.f, gacc1 = 0.f, gacc2 = 0.f;

        // ---- streaming with one-token lookahead, double-buffered (12 LDG in flight) ----
        float va[12], vb[12];
        LOAD_TOK(va, ts);

#pragma unroll 1
        for (int t = ts; t < te; ) {
            if (t + 1 < te) LOAD_TOK(vb, t + 1);
            {
                float e0, e1, e2;
                ESUM(va, e0, e1, e2);
                FLUSH(t, e0, e1, e2);
            }
            ++t;
            if (t >= te) break;

            if (t + 1 < te) LOAD_TOK(va, t + 1);
            {
                float e0, e1, e2;
                ESUM(vb, e0, e1, e2);
                FLUSH(t, e0, e1, e2);
            }
            ++t;
        }

        // ---- final flushes ----
        {
            const int wo = cur_g * D;
            wout[wo] = wacc0; wout[wo + 256] = wacc1; wout[wo + 512] = wacc2;
            const int mysg = s_sg[cur_g];
            if (mysg != cur_sg) {
                const int go = cur_sg * D;
                atomicAdd(&gout[go], gacc0);
                atomicAdd(&gout[go + 256], gacc1);
                atomicAdd(&gout[go + 512], gacc2);
                gacc0 = gacc1 = gacc2 = 0.f;
                cur_sg = mysg;
            }
            gacc0 += wacc0; gacc1 += wacc1; gacc2 += wacc2;
        }
        {
            const int go = cur_sg * D;
            atomicAdd(&gout[go], gacc0);
            atomicAdd(&gout[go + 256], gacc1);
            atomicAdd(&gout[go + 512], gacc2);
        }

        // trailing word gap owned by this chunk
        {
            const int nextw = (te < S) ? s_tg[te] : S;
            for (int z = cur_g + 1; z < nextw; ++z) {
                const int zo = z * D;
                wout[zo] = 0.f; wout[zo + 256] = 0.f; wout[zo + 512] = 0.f;
            }
        }

        // sentence partial: mean over 512 padded word slots == total sum / 512
        {
            float* sp = out + OFF_SENT + b * D + tid;
            atomicAdd(sp,       sent0 * (1.0f / 512.0f));
            atomicAdd(sp + 256, sent1 * (1.0f / 512.0f));
            atomicAdd(sp + 512, sent2 * (1.0f / 512.0f));
        }
    }

    // seg_mask (sorted segment_ids -> max is last element); one CTA per batch
    if (blockIdx.x == 0 && tid < G) {
        const int seg_num = s_sg[S - 1] + 1;
        out[OFF_MASK + (size_t)b * G + tid] = (tid >= seg_num) ? 1.0f : 0.0f;
    }
}

extern "C" void kernel_launch(void* const* d_in, const int* in_sizes, int n_in,
                              void* d_out, int out_size)
{
    const float* emb = (const float*)d_in[0];   // embeddings      [B,L,S,D] f32
    const int*   tg  = (const int*)  d_in[1];   // token_group_ids [B,S] i32
    const int*   sg  = (const int*)  d_in[2];   // segment_ids     [B,S] i32
    float*       out = (float*)d_out;

    // zero the atomically-accumulated region (sent + seg) via a memset node
    cudaMemsetAsync(out + OFF_SENT, 0, ZERO_N * sizeof(float));

    dim3 grid(NCHUNK, B);   // (18, 32) = 576 CTAs ~= one wave at occ 4
    bert_agg_kernel<<<grid, 256>>>(emb, tg, sg, out);
}

// round 15
// speedup vs baseline: 1.1462x; 1.1462x over previous
#include <cuda_runtime.h>
#include <stdint.h>

// Problem shape (static)
#define B 32
#define L 4
#define S 512
#define D 768
#define G 24        // NUM_SEGMENTS
#define NCHUNK 6
#define TPC (S / NCHUNK)

// Output layout (float32, tuple-order concat):
//   word [B,S,D] | sent [B,D] | seg [B,G,D] | mask [B,G]
#define OFF_SENT ((size_t)B * S * D)
#define OFF_SEG  (OFF_SENT + (size_t)B * D)
#define OFF_MASK (OFF_SEG + (size_t)B * G * D)
// only the sentence region needs zero-init now (accumulated via atomics)
#define ZERO_N   ((size_t)B * D)

// grid: (6 dslices * NCHUNK, 32 batches), block: 128 threads (1 d column each)
__global__ void __launch_bounds__(128, 8)
bert_agg_kernel(const float* __restrict__ emb,
                const int*   __restrict__ tg,
                const int*   __restrict__ sg,
                float*       __restrict__ out)
{
    const int b      = blockIdx.y;
    const int chunk  = blockIdx.x / 6;
    const int dslice = blockIdx.x % 6;
    const int d      = dslice * 128 + threadIdx.x;

    __shared__ int s_tg[S];
    __shared__ int s_sg[S];
    for (int i = threadIdx.x; i < S; i += 128) {
        s_tg[i] = tg[b * S + i];
        s_sg[i] = sg[b * S + i];
    }
    __syncthreads();

    // ---- chunk bounds snapped to SEGMENT boundaries (block-uniform) ----
    // (a segment boundary is necessarily a word boundary, so words stay
    //  chunk-exclusive too; segments become chunk-exclusive -> no seg atomics)
    int ts = chunk * TPC;
    while (ts > 0 && ts < S && s_sg[s_tg[ts]] == s_sg[s_tg[ts - 1]]) ++ts;
    int te;
    if (chunk == NCHUNK - 1) {
        te = S;
    } else {
        te = (chunk + 1) * TPC;
        while (te < S && s_sg[s_tg[te]] == s_sg[s_tg[te - 1]]) ++te;
    }

    // 32-bit offsets (max index < 2^26)
    const int    LS  = S * D;                 // layer stride in floats
    const float* ep  = emb + (b * L * S * D) + d;
    float*      wout = out + (b * S * D) + d;
    float*      gout = out + OFF_SEG + (b * G * D) + d;

    if (ts < te) {
        // leading gaps (only the chunk starting at token 0)
        if (ts == 0) {
            const int firstw = s_tg[0];
            for (int z = 0; z < firstw; ++z) __stcs(&wout[z * D], 0.f);
            const int firstsg = s_sg[firstw];
            for (int z = 0; z < firstsg; ++z) gout[z * D] = 0.f;
        }

        float sent   = 0.f;
        int   cur_g  = s_tg[ts];
        float wacc   = 0.f;
        int   cur_sg = s_sg[cur_g];
        float gacc   = 0.f;

        // ---- streaming: 4 tokens x 4 layers in flight (16 independent LDG.32) ----
        float v0[4], v1[4], v2[4], v3[4];
#pragma unroll
        for (int i = 0; i < 4; ++i) {
            const int t = (ts + i < S) ? (ts + i) : (S - 1);
            const float* p = ep + t * D;
            v0[i] = __ldcs(p);
            v1[i] = __ldcs(p + LS);
            v2[i] = __ldcs(p + 2 * LS);
            v3[i] = __ldcs(p + 3 * LS);
        }

#pragma unroll 1
        for (int tc = ts; tc < te; tc += 4) {
            float e[4];
#pragma unroll
            for (int i = 0; i < 4; ++i)
                e[i] = (v0[i] + v1[i]) + (v2[i] + v3[i]);

            const int tn = tc + 4;
            if (tn < te) {
#pragma unroll
                for (int i = 0; i < 4; ++i) {
                    const int t = (tn + i < S) ? (tn + i) : (S - 1);
                    const float* p = ep + t * D;
                    v0[i] = __ldcs(p);
                    v1[i] = __ldcs(p + LS);
                    v2[i] = __ldcs(p + 2 * LS);
                    v3[i] = __ldcs(p + 3 * LS);
                }
            }

            const int n = te - tc;
#pragma unroll
            for (int i = 0; i < 4; ++i) {
                if (i < n) {
                    const int g = s_tg[tc + i];
                    if (g != cur_g) {
                        // flush completed word run (chunk-exclusive)
                        __stcs(&wout[cur_g * D], wacc);
                        const int mysg = s_sg[cur_g];
                        if (mysg != cur_sg) {
                            // flush completed segment (chunk-exclusive: plain store)
                            gout[cur_sg * D] = gacc;
                            for (int z = cur_sg + 1; z < mysg; ++z)
                                gout[z * D] = 0.f;
                            gacc   = 0.f;
                            cur_sg = mysg;
                        }
                        gacc += wacc;
                        // zero skipped word slots interior to this chunk's range
                        for (int z = cur_g + 1; z < g; ++z)
                            __stcs(&wout[z * D], 0.f);
                        wacc  = 0.f;
                        cur_g = g;
                    }
                    wacc += e[i];
                    sent += e[i];
                }
            }
        }

        // ---- final flushes (all chunk-exclusive) ----
        __stcs(&wout[cur_g * D], wacc);
        {
            const int mysg = s_sg[cur_g];
            if (mysg != cur_sg) {
                gout[cur_sg * D] = gacc;
                for (int z = cur_sg + 1; z < mysg; ++z)
                    gout[z * D] = 0.f;
                gacc   = 0.f;
                cur_sg = mysg;
            }
            gacc += wacc;
        }
        gout[cur_sg * D] = gacc;

        // trailing gaps owned by this chunk
        {
            const int nextw = (te < S) ? s_tg[te] : S;
            for (int z = cur_g + 1; z < nextw; ++z)
                __stcs(&wout[z * D], 0.f);
            const int nextsg = (te < S) ? s_sg[s_tg[te]] : G;
            for (int z = cur_sg + 1; z < nextsg; ++z)
                gout[z * D] = 0.f;
        }

        // sentence partial: mean over 512 padded word slots == total sum / 512
        atomicAdd(&out[OFF_SENT + b * D + d], sent * (1.0f / 512.0f));
    }

    // seg_mask (sorted segment_ids -> max is last element); one CTA per batch
    if (blockIdx.x == 0 && threadIdx.x < G) {
        const int seg_num = s_sg[S - 1] + 1;
        out[OFF_MASK + (size_t)b * G + threadIdx.x] =
            (threadIdx.x >= seg_num) ? 1.0f : 0.0f;
    }
}

extern "C" void kernel_launch(void* const* d_in, const int* in_sizes, int n_in,
                              void* d_out, int out_size)
{
    const float* emb = (const float*)d_in[0];   // embeddings      [B,L,S,D] f32
    const int*   tg  = (const int*)  d_in[1];   // token_group_ids [B,S] i32
    const int*   sg  = (const int*)  d_in[2];   // segment_ids     [B,S] i32
    float*       out = (float*)d_out;

    // zero only the sentence region (atomic accumulation target)
    cudaMemsetAsync(out + OFF_SENT, 0, ZERO_N * sizeof(float));

    dim3 grid(6 * NCHUNK, B);   // (36, 32) = 1152 CTAs ~= one wave at occ 8
    bert_agg_kernel<<<grid, 128>>>(emb, tg, sg, out);
}